// round 1
// baseline (speedup 1.0000x reference)
#include <cuda_runtime.h>
#include <cstdint>
#include <cstddef>

#define B_BATCH 1024
#define T_STEPS 100
#define N_IN    784
#define N_HID   100
#define N_OUT   10
#define M_TOT   (B_BATCH * T_STEPS)   // 102400

// Scratch for Y = X @ W1^T  (102400 x 100 fp32 = 41 MB)
__device__ float g_Y[(size_t)M_TOT * N_HID];

// ---------------- helpers: packed fp32x2 (Blackwell FFMA2) ----------------
static __device__ __forceinline__ unsigned long long lds_u64(uint32_t addr) {
    unsigned long long v;
    asm volatile("ld.shared.b64 %0, [%1];" : "=l"(v) : "r"(addr));
    return v;
}
static __device__ __forceinline__ unsigned long long fma2(
    unsigned long long a, unsigned long long b, unsigned long long c) {
    unsigned long long d;
    asm("fma.rn.f32x2 %0, %1, %2, %3;" : "=l"(d) : "l"(a), "l"(b), "l"(c));
    return d;
}

// ---------------- GEMM: Y[m, n] = sum_k X[m,k] * W1[n,k] ----------------
// Tile: BM=64 rows x BN=128 cols (cols 100..127 wasted, masked at store).
// a-operands stored duplicated (x,x) as float2 -> direct ld.shared.b64.
// b-operands paired as (col q, col q+64), q in [0,64) -> conflict-free LDS.
#define BM 64
#define BK 16
#define XS_STR 65   // float2 stride per k-row (pad)
#define WS_STR 64   // float2 (pair) stride per k-row

__global__ __launch_bounds__(256, 2) void gemm_y_kernel(
    const float* __restrict__ X, const float* __restrict__ W1)
{
    __shared__ float2 Xs[BK * XS_STR];
    __shared__ float2 Ws[BK * WS_STR];

    const int tid = threadIdx.x;
    const int tx  = tid & 15;     // col group: pairs q = tx + 16j
    const int ty  = tid >> 4;     // row group: rows ty*4 .. ty*4+3
    const int m0  = blockIdx.x * BM;

    unsigned long long acc[4][4];
#pragma unroll
    for (int r = 0; r < 4; ++r)
#pragma unroll
        for (int j = 0; j < 4; ++j) acc[r][j] = 0ull;

    // X tile loader mapping: 4 threads per row, coalesced float4
    const int lm  = tid >> 2;     // 0..63
    const int lk4 = tid & 3;      // 0..3 (float4 slot within 16-float chunk)
    const float4* Xg = reinterpret_cast<const float4*>(
        X + (size_t)(m0 + lm) * N_IN) + lk4;

    // W tile loader mapping: rows h0 (0..63) and h1 (64..127, guarded <100)
    const int h0  = tid >> 2;     // 0..63
    const int wk4 = tid & 3;
    const int h1  = h0 + 64;      // 64..127
    const float4* Wg0 = reinterpret_cast<const float4*>(
        W1 + (size_t)h0 * N_IN) + wk4;
    const float4* Wg1 = (h1 < N_HID)
        ? reinterpret_cast<const float4*>(W1 + (size_t)h1 * N_IN) + wk4
        : nullptr;

    const uint32_t xs_base = (uint32_t)__cvta_generic_to_shared(Xs);
    const uint32_t ws_base = (uint32_t)__cvta_generic_to_shared(Ws);
    float* Wf = reinterpret_cast<float*>(Ws);

    for (int kc = 0; kc < N_IN / 4; kc += BK / 4) {   // 49 chunks
        float4 xv  = Xg[kc];
        float4 wv0 = Wg0[kc];
        float4 wv1 = make_float4(0.f, 0.f, 0.f, 0.f);
        if (Wg1) wv1 = Wg1[kc];

        __syncthreads();   // previous chunk's compute done

        {   // store X duplicated: Xs[k][m] = (x, x)
            float v[4] = {xv.x, xv.y, xv.z, xv.w};
#pragma unroll
            for (int j = 0; j < 4; ++j) {
                int k = lk4 * 4 + j;
                Xs[k * XS_STR + lm] = make_float2(v[j], v[j]);
            }
        }
        {   // store W pairs: pair q holds (W1[q][k], W1[q+64][k]); zeros for h>=100
            float a0[4] = {wv0.x, wv0.y, wv0.z, wv0.w};
            float a1[4] = {wv1.x, wv1.y, wv1.z, wv1.w};
#pragma unroll
            for (int j = 0; j < 4; ++j) {
                int k = wk4 * 4 + j;
                Wf[(k * WS_STR + h0) * 2 + 0]        = a0[j];
                Wf[(k * WS_STR + (h1 - 64)) * 2 + 1] = a1[j];
            }
        }
        __syncthreads();

#pragma unroll
        for (int k = 0; k < BK; ++k) {
            const uint32_t xa = xs_base + (uint32_t)(k * XS_STR + ty * 4) * 8u;
            const uint32_t wa = ws_base + (uint32_t)(k * WS_STR + tx) * 8u;
            unsigned long long a0 = lds_u64(xa);
            unsigned long long a1 = lds_u64(xa + 8);
            unsigned long long a2 = lds_u64(xa + 16);
            unsigned long long a3 = lds_u64(xa + 24);
            unsigned long long b0 = lds_u64(wa);
            unsigned long long b1 = lds_u64(wa + 16 * 8);
            unsigned long long b2 = lds_u64(wa + 32 * 8);
            unsigned long long b3 = lds_u64(wa + 48 * 8);
            acc[0][0] = fma2(a0, b0, acc[0][0]);
            acc[0][1] = fma2(a0, b1, acc[0][1]);
            acc[0][2] = fma2(a0, b2, acc[0][2]);
            acc[0][3] = fma2(a0, b3, acc[0][3]);
            acc[1][0] = fma2(a1, b0, acc[1][0]);
            acc[1][1] = fma2(a1, b1, acc[1][1]);
            acc[1][2] = fma2(a1, b2, acc[1][2]);
            acc[1][3] = fma2(a1, b3, acc[1][3]);
            acc[2][0] = fma2(a2, b0, acc[2][0]);
            acc[2][1] = fma2(a2, b1, acc[2][1]);
            acc[2][2] = fma2(a2, b2, acc[2][2]);
            acc[2][3] = fma2(a2, b3, acc[2][3]);
            acc[3][0] = fma2(a3, b0, acc[3][0]);
            acc[3][1] = fma2(a3, b1, acc[3][1]);
            acc[3][2] = fma2(a3, b2, acc[3][2]);
            acc[3][3] = fma2(a3, b3, acc[3][3]);
        }
    }

    // epilogue: pair (q, q+64); q in [0,64) always valid, q+64 masked
#pragma unroll
    for (int r = 0; r < 4; ++r) {
        const int gm = m0 + ty * 4 + r;
        float* Yrow = g_Y + (size_t)gm * N_HID;
#pragma unroll
        for (int j = 0; j < 4; ++j) {
            const int q = tx + 16 * j;
            const uint32_t lo = (uint32_t)(acc[r][j] & 0xffffffffull);
            const uint32_t hi = (uint32_t)(acc[r][j] >> 32);
            Yrow[q] = __uint_as_float(lo);
            if (q + 64 < N_HID) Yrow[q + 64] = __uint_as_float(hi);
        }
    }
}

// ---------------- scan: one warp per batch row, T=100 steps ----------------
__global__ __launch_bounds__(128) void scan_kernel(
    const float* __restrict__ w_syn1, const float* __restrict__ b1,
    const float* __restrict__ w_syn2, const float* __restrict__ W2,
    const float* __restrict__ b2, float* __restrict__ out)
{
    const int gwarp = (int)((blockIdx.x * blockDim.x + threadIdx.x) >> 5);
    const int lane  = threadIdx.x & 31;
    if (gwarp >= B_BATCH) return;
    const int b = gwarp;

    const float inv1 = 1.f / (1.f + expf(-w_syn1[0]));   // sigmoid(w)
    const float inv2 = 1.f / (1.f + expf(-w_syn2[0]));

    float hs1[4] = {0.f, 0.f, 0.f, 0.f};
    float v1[4]  = {0.f, 0.f, 0.f, 0.f};
    float b1r[4];
    float w2r[4][N_OUT];
#pragma unroll
    for (int k = 0; k < 4; ++k) {
        const int h = lane + 32 * k;
        const bool valid = h < N_HID;
        b1r[k] = valid ? b1[h] : 0.f;
#pragma unroll
        for (int o = 0; o < N_OUT; ++o)
            w2r[k][o] = valid ? W2[o * N_HID + h] : 0.f;
    }
    float hs2[N_OUT], v2[N_OUT], b2r[N_OUT];
#pragma unroll
    for (int o = 0; o < N_OUT; ++o) { hs2[o] = 0.f; v2[o] = 0.f; b2r[o] = b2[o]; }

    const float* Yb = g_Y + (size_t)b * T_STEPS * N_HID;

    float y[4];
#pragma unroll
    for (int k = 0; k < 4; ++k) {
        const int h = lane + 32 * k;
        y[k] = (h < N_HID) ? Yb[h] : 0.f;
    }

    for (int t = 0; t < T_STEPS; ++t) {
        // prefetch next step's Y
        float yn[4] = {0.f, 0.f, 0.f, 0.f};
        if (t + 1 < T_STEPS) {
            const float* Yt = Yb + (size_t)(t + 1) * N_HID;
#pragma unroll
            for (int k = 0; k < 4; ++k) {
                const int h = lane + 32 * k;
                yn[k] = (h < N_HID) ? Yt[h] : 0.f;
            }
        }

        float part[N_OUT];
#pragma unroll
        for (int o = 0; o < N_OUT; ++o) part[o] = 0.f;

#pragma unroll
        for (int k = 0; k < 4; ++k) {
            // SynapseFilter 1 (linearized): s - s*inv + in
            hs1[k] = (hs1[k] - hs1[k] * inv1) + y[k];
            const float h1 = hs1[k] + b1r[k];
            // LIF 1: v += (h - v)/2 ; hard reset at threshold 1.0
            v1[k] = v1[k] + (h1 - v1[k]) * 0.5f;
            const float spk = (v1[k] >= 1.0f) ? 1.f : 0.f;
            v1[k] = v1[k] * (1.f - spk);
            // partial sp1 @ W2^T
#pragma unroll
            for (int o = 0; o < N_OUT; ++o)
                part[o] = fmaf(spk, w2r[k][o], part[o]);
        }

        // butterfly reduce -> every lane has full h2 partials
#pragma unroll
        for (int off = 16; off > 0; off >>= 1)
#pragma unroll
            for (int o = 0; o < N_OUT; ++o)
                part[o] += __shfl_xor_sync(0xffffffffu, part[o], off);

#pragma unroll
        for (int o = 0; o < N_OUT; ++o) {
            hs2[o] = (hs2[o] - hs2[o] * inv2) + part[o];
            const float h2 = hs2[o] + b2r[o];
            v2[o] = v2[o] + (h2 - v2[o]) * 0.5f;
            // LIF2 spike threshold 0, soft reset subtracts spike*0 -> no-op
        }

#pragma unroll
        for (int k = 0; k < 4; ++k) y[k] = yn[k];
    }

    if (lane == 0) {
#pragma unroll
        for (int o = 0; o < N_OUT; ++o) out[b * N_OUT + o] = v2[o];
    }
}

// ---------------- entry ----------------
extern "C" void kernel_launch(void* const* d_in, const int* in_sizes, int n_in,
                              void* d_out, int out_size) {
    const float* x   = (const float*)d_in[0];  // [1024, 100, 784]
    const float* w1s = (const float*)d_in[1];  // scalar
    const float* W1  = (const float*)d_in[2];  // [100, 784]
    const float* b1  = (const float*)d_in[3];  // [100]
    const float* w2s = (const float*)d_in[4];  // scalar
    const float* W2  = (const float*)d_in[5];  // [10, 100]
    const float* b2  = (const float*)d_in[6];  // [10]
    float* out = (float*)d_out;                // [1024, 10]

    gemm_y_kernel<<<M_TOT / BM, 256>>>(x, W1);
    scan_kernel<<<(B_BATCH * 32) / 128, 128>>>(w1s, b1, w2s, W2, b2, out);
}

// round 3
// speedup vs baseline: 1.2221x; 1.2221x over previous
#include <cuda_runtime.h>
#include <cstdint>
#include <cstddef>

#define B_BATCH 1024
#define T_STEPS 100
#define N_IN    784
#define N_HID   100
#define N_OUT   10
#define M_TOT   (B_BATCH * T_STEPS)   // 102400

// Scratch: Y = X@W1^T, SP = spikes, H2T = (SP@W2^T) transposed
__device__ float g_Y [(size_t)M_TOT * N_HID];
__device__ float g_SP[(size_t)M_TOT * N_HID];
__device__ float g_H2T[(size_t)N_OUT * M_TOT];

// ---------------- packed fp32x2 helpers ----------------
static __device__ __forceinline__ unsigned long long lds_u64(uint32_t addr) {
    unsigned long long v;
    asm volatile("ld.shared.b64 %0, [%1];" : "=l"(v) : "r"(addr));
    return v;
}
static __device__ __forceinline__ unsigned long long fma2(
    unsigned long long a, unsigned long long b, unsigned long long c) {
    unsigned long long d;
    asm("fma.rn.f32x2 %0, %1, %2, %3;" : "=l"(d) : "l"(a), "l"(b), "l"(c));
    return d;
}

// ================= GEMM1: Y[m,n] = sum_k X[m,k]*W1[n,k] =================
// Tile 128 rows x 100 cols (50 pairs (q, q+50)) -> zero column waste.
// 320 threads = (x:10 pair-groups) x (y:32 row-groups).
// Thread tile: 4 rows (y+32r) x 5 pairs (x+10j) = 20 FFMA2 per k.
#define BMg  128
#define PQ   50
#define BKg  16
#define XSTR 133   // float2 per k-row (pad vs store conflicts)
#define WSTR 53

__global__ __launch_bounds__(320, 2) void gemm1_kernel(
    const float* __restrict__ X, const float* __restrict__ W1)
{
    __shared__ float2 Xs[BKg * XSTR];
    __shared__ float2 Ws[BKg * WSTR];

    const int x   = threadIdx.x;          // 0..9
    const int y   = threadIdx.y;          // 0..31
    const int tid = y * 10 + x;           // 0..319
    const int m0  = blockIdx.x * BMg;

    unsigned long long acc[4][5];
#pragma unroll
    for (int r = 0; r < 4; ++r)
#pragma unroll
        for (int j = 0; j < 5; ++j) acc[r][j] = 0ull;

    // X tile loader: 128 rows x 4 float4-slots = 512 units, two passes
    const int r1 = tid >> 2, s1 = tid & 3;
    const int xidx2 = tid + 320;
    const int r2 = xidx2 >> 2, s2 = xidx2 & 3;
    const bool p2 = (xidx2 < 512);        // tid < 192
    // W tile loader: 100 rows x 4 slots = 400 units, two passes
    const int hw1 = tid >> 2, sw1 = tid & 3;        // units 0..319 -> rows 0..79
    const int widx2 = tid + 320;                    // units 320..399 -> rows 80..99
    const int hw2 = widx2 >> 2, sw2 = widx2 & 3;
    const bool pw2 = (widx2 < 400);                 // tid < 80

    const float4* X4 = reinterpret_cast<const float4*>(X);
    const float4* W4 = reinterpret_cast<const float4*>(W1);

    const size_t xoff1 = (size_t)(m0 + r1) * (N_IN / 4) + s1;
    const size_t xoff2 = (size_t)(m0 + (p2 ? r2 : 0)) * (N_IN / 4) + s2;
    const size_t woff1 = (size_t)hw1 * (N_IN / 4) + sw1;
    const size_t woff2 = (size_t)(pw2 ? hw2 : 0) * (N_IN / 4) + sw2;

    const uint32_t xs_base = (uint32_t)__cvta_generic_to_shared(Xs);
    const uint32_t ws_base = (uint32_t)__cvta_generic_to_shared(Ws);

    for (int kc = 0; kc < N_IN / BKg; ++kc) {   // 49 chunks of 16 k
        float4 xa = X4[xoff1 + (size_t)kc * 4];
        float4 xb = make_float4(0.f, 0.f, 0.f, 0.f);
        if (p2) xb = X4[xoff2 + (size_t)kc * 4];
        float4 wa = W4[woff1 + (size_t)kc * 4];
        float4 wb = make_float4(0.f, 0.f, 0.f, 0.f);
        if (pw2) wb = W4[woff2 + (size_t)kc * 4];

        __syncthreads();   // previous chunk fully consumed

        {   // X duplicated (v, v)
            float v[4] = {xa.x, xa.y, xa.z, xa.w};
#pragma unroll
            for (int j = 0; j < 4; ++j)
                Xs[(s1 * 4 + j) * XSTR + r1] = make_float2(v[j], v[j]);
        }
        if (p2) {
            float v[4] = {xb.x, xb.y, xb.z, xb.w};
#pragma unroll
            for (int j = 0; j < 4; ++j)
                Xs[(s2 * 4 + j) * XSTR + r2] = make_float2(v[j], v[j]);
        }
        {   // W pass 1: rows 0..79
            float v[4] = {wa.x, wa.y, wa.z, wa.w};
            const int q    = (hw1 < PQ) ? hw1 : hw1 - PQ;
            const int half = (hw1 < PQ) ? 0 : 1;
#pragma unroll
            for (int j = 0; j < 4; ++j)
                reinterpret_cast<float*>(&Ws[(sw1 * 4 + j) * WSTR + q])[half] = v[j];
        }
        if (pw2) {  // W pass 2: rows 80..99 (half 1 of pairs 30..49)
            float v[4] = {wb.x, wb.y, wb.z, wb.w};
            const int q = hw2 - PQ;   // hw2 in 80..99 -> q 30..49
#pragma unroll
            for (int j = 0; j < 4; ++j)
                reinterpret_cast<float*>(&Ws[(sw2 * 4 + j) * WSTR + q])[1] = v[j];
        }
        __syncthreads();

#pragma unroll
        for (int k = 0; k < BKg; ++k) {
            const uint32_t xaddr = xs_base + (uint32_t)(k * XSTR + y) * 8u;
            const uint32_t waddr = ws_base + (uint32_t)(k * WSTR + x) * 8u;
            unsigned long long a[4], bb[5];
#pragma unroll
            for (int r = 0; r < 4; ++r) a[r]  = lds_u64(xaddr + (uint32_t)(32 * r) * 8u);
#pragma unroll
            for (int j = 0; j < 5; ++j) bb[j] = lds_u64(waddr + (uint32_t)(10 * j) * 8u);
#pragma unroll
            for (int r = 0; r < 4; ++r)
#pragma unroll
                for (int j = 0; j < 5; ++j)
                    acc[r][j] = fma2(a[r], bb[j], acc[r][j]);
        }
    }

    // epilogue: pair (q, q+50), all indices valid (N=100 exactly)
#pragma unroll
    for (int r = 0; r < 4; ++r) {
        const int m = m0 + y + 32 * r;
        float* row = g_Y + (size_t)m * N_HID;
#pragma unroll
        for (int j = 0; j < 5; ++j) {
            const int q = x + 10 * j;
            row[q]      = __uint_as_float((uint32_t)(acc[r][j] & 0xffffffffull));
            row[q + PQ] = __uint_as_float((uint32_t)(acc[r][j] >> 32));
        }
    }
}

// ============ Phase A: layer-1 scan (local per hidden unit) ============
// warp = batch row b; lane < 25 handles h = 4*lane .. 4*lane+3
__global__ __launch_bounds__(128) void scan1_kernel(
    const float* __restrict__ w_syn1, const float* __restrict__ b1)
{
    const int gw   = (int)((blockIdx.x * blockDim.x + threadIdx.x) >> 5);
    const int lane = threadIdx.x & 31;
    if (gw >= B_BATCH || lane >= 25) return;

    const float inv1 = 1.f / (1.f + expf(-w_syn1[0]));
    const int h0 = lane * 4;
    const float4 bv = *reinterpret_cast<const float4*>(b1 + h0);
    const float ba[4] = {bv.x, bv.y, bv.z, bv.w};

    float hs[4] = {0.f, 0.f, 0.f, 0.f};
    float v [4] = {0.f, 0.f, 0.f, 0.f};

    const float* Yb = g_Y  + (size_t)gw * T_STEPS * N_HID + h0;
    float*       Sb = g_SP + (size_t)gw * T_STEPS * N_HID + h0;

    for (int t = 0; t < T_STEPS; ++t) {
        const float4 yv = *reinterpret_cast<const float4*>(Yb + (size_t)t * N_HID);
        const float ya[4] = {yv.x, yv.y, yv.z, yv.w};
        float sp[4];
#pragma unroll
        for (int i = 0; i < 4; ++i) {
            hs[i] = (hs[i] - hs[i] * inv1) + ya[i];     // SynapseFilter 1
            const float h1 = hs[i] + ba[i];
            v[i] = v[i] + (h1 - v[i]) * 0.5f;           // LIF decay (tau=2)
            const float s = (v[i] >= 1.0f) ? 1.f : 0.f; // threshold 1.0
            v[i] = v[i] * (1.f - s);                    // hard reset
            sp[i] = s;
        }
        *reinterpret_cast<float4*>(Sb + (size_t)t * N_HID) =
            make_float4(sp[0], sp[1], sp[2], sp[3]);
    }
}

// ============ Phase B: H2T[o, m] = sum_h SP[m,h]*W2[o,h] ============
__global__ __launch_bounds__(256) void gemm2_kernel(const float* __restrict__ W2)
{
    __shared__ float4 W2s[N_OUT * 25];
    const int tid = threadIdx.x;
    if (tid < N_OUT * 25)
        W2s[tid] = reinterpret_cast<const float4*>(W2)[tid];
    __syncthreads();

    const int m = blockIdx.x * 256 + tid;   // grid 400 -> exactly 102400
    const float4* sp = reinterpret_cast<const float4*>(g_SP + (size_t)m * N_HID);

    float acc[N_OUT];
#pragma unroll
    for (int o = 0; o < N_OUT; ++o) acc[o] = 0.f;

#pragma unroll 5
    for (int k4 = 0; k4 < 25; ++k4) {
        const float4 s = sp[k4];
#pragma unroll
        for (int o = 0; o < N_OUT; ++o) {
            const float4 w = W2s[o * 25 + k4];
            acc[o] = fmaf(s.x, w.x, acc[o]);
            acc[o] = fmaf(s.y, w.y, acc[o]);
            acc[o] = fmaf(s.z, w.z, acc[o]);
            acc[o] = fmaf(s.w, w.w, acc[o]);
        }
    }
#pragma unroll
    for (int o = 0; o < N_OUT; ++o)
        g_H2T[(size_t)o * M_TOT + m] = acc[o];  // transposed, coalesced
}

// ============ Phase C: layer-2 scan, thread = (b, o) ============
__global__ __launch_bounds__(256) void scan2_kernel(
    const float* __restrict__ w_syn2, const float* __restrict__ b2,
    float* __restrict__ out)
{
    const int gt = blockIdx.x * 256 + threadIdx.x;   // 0..10239
    const int o  = gt >> 10;    // 0..9
    const int b  = gt & 1023;

    const float inv2 = 1.f / (1.f + expf(-w_syn2[0]));
    const float bo = b2[o];
    const float* h = g_H2T + (size_t)o * M_TOT + (size_t)b * T_STEPS;

    float hs = 0.f, v = 0.f;
#pragma unroll 4
    for (int t = 0; t < T_STEPS; ++t) {
        const float p = h[t];
        hs = (hs - hs * inv2) + p;          // SynapseFilter 2
        const float h2 = hs + bo;
        v = v + (h2 - v) * 0.5f;            // LIF 2 (soft reset at thr 0 -> no-op)
    }
    out[b * N_OUT + o] = v;
}

// ---------------- entry ----------------
extern "C" void kernel_launch(void* const* d_in, const int* in_sizes, int n_in,
                              void* d_out, int out_size) {
    const float* x   = (const float*)d_in[0];  // [1024, 100, 784]
    const float* w1s = (const float*)d_in[1];  // scalar
    const float* W1  = (const float*)d_in[2];  // [100, 784]
    const float* b1  = (const float*)d_in[3];  // [100]
    const float* w2s = (const float*)d_in[4];  // scalar
    const float* W2  = (const float*)d_in[5];  // [10, 100]
    const float* b2  = (const float*)d_in[6];  // [10]
    float* out = (float*)d_out;                // [1024, 10]

    gemm1_kernel<<<M_TOT / BMg, dim3(10, 32, 1)>>>(x, W1);
    scan1_kernel<<<B_BATCH / 4, 128>>>(w1s, b1);
    gemm2_kernel<<<M_TOT / 256, 256>>>(W2);
    scan2_kernel<<<(B_BATCH * N_OUT) / 256, 256>>>(w2s, b2, out);
}

// round 5
// speedup vs baseline: 1.3046x; 1.0675x over previous
#include <cuda_runtime.h>
#include <cstdint>
#include <cstddef>

#define B_BATCH 1024
#define T_STEPS 100
#define N_IN    784
#define N_HID   100
#define N_OUT   10
#define M_TOT   (B_BATCH * T_STEPS)   // 102400

#define NKS   98          // 784 / 8 k-steps
#define NMT   7           // 112 padded output rows / 16
#define NPAD  112

// Scratch
__device__ float g_YT [(size_t)N_HID * M_TOT];   // Y^T  [100][102400]
__device__ float g_SPT[(size_t)N_HID * M_TOT];   // SP^T [100][102400]
__device__ float g_H2T[(size_t)N_OUT * M_TOT];   // H2^T [10][102400]
// Packed tf32 A-fragments of W1: [NKS][NMT][32 lanes] x float4 (a0..a3)
__device__ float4 g_ApkHi[NKS * NMT * 32];
__device__ float4 g_ApkLo[NKS * NMT * 32];

// ---------------- tf32 helpers ----------------
static __device__ __forceinline__ uint32_t f2tf32(float x) {
    uint32_t r;
    asm("cvt.rna.tf32.f32 %0, %1;" : "=r"(r) : "f"(x));
    return r;
}
static __device__ __forceinline__ void split_tf32(float x, uint32_t& hi, uint32_t& lo) {
    hi = f2tf32(x);
    lo = f2tf32(x - __uint_as_float(hi));
}
static __device__ __forceinline__ void mma_tf32(
    float& d0, float& d1, float& d2, float& d3,
    uint32_t a0, uint32_t a1, uint32_t a2, uint32_t a3,
    uint32_t b0, uint32_t b1)
{
    asm volatile(
        "mma.sync.aligned.m16n8k8.row.col.f32.tf32.tf32.f32 "
        "{%0,%1,%2,%3}, {%4,%5,%6,%7}, {%8,%9}, {%0,%1,%2,%3};\n"
        : "+f"(d0), "+f"(d1), "+f"(d2), "+f"(d3)
        : "r"(a0), "r"(a1), "r"(a2), "r"(a3), "r"(b0), "r"(b1));
}

// ============ Prep: pack W1 into tf32 A-fragments (hi/lo) ============
// thread -> (s, mt, lane). a0:(row=q, k=r) a1:(q+8, r) a2:(q, r+4) a3:(q+8, r+4)
__global__ __launch_bounds__(256) void prep_a_kernel(const float* __restrict__ W1)
{
    const int gid = blockIdx.x * 256 + threadIdx.x;
    if (gid >= NKS * NMT * 32) return;
    const int lane = gid & 31;
    const int mt   = (gid >> 5) % NMT;
    const int s    = (gid >> 5) / NMT;
    const int q = lane >> 2, r = lane & 3;
    const int n0 = mt * 16 + q;       // W row for a0/a2
    const int n1 = n0 + 8;            // W row for a1/a3
    const int k0 = s * 8 + r;

    const float v0 = (n0 < N_HID) ? W1[(size_t)n0 * N_IN + k0]     : 0.f;
    const float v1 = (n1 < N_HID) ? W1[(size_t)n1 * N_IN + k0]     : 0.f;
    const float v2 = (n0 < N_HID) ? W1[(size_t)n0 * N_IN + k0 + 4] : 0.f;
    const float v3 = (n1 < N_HID) ? W1[(size_t)n1 * N_IN + k0 + 4] : 0.f;

    uint32_t h0, l0, h1, l1, h2, l2, h3, l3;
    split_tf32(v0, h0, l0); split_tf32(v1, h1, l1);
    split_tf32(v2, h2, l2); split_tf32(v3, h3, l3);

    float4 fh, fl;
    fh.x = __uint_as_float(h0); fh.y = __uint_as_float(h1);
    fh.z = __uint_as_float(h2); fh.w = __uint_as_float(h3);
    fl.x = __uint_as_float(l0); fl.y = __uint_as_float(l1);
    fl.z = __uint_as_float(l2); fl.w = __uint_as_float(l3);
    g_ApkHi[gid] = fh;
    g_ApkLo[gid] = fl;
}

// ============ GEMM1 (mma.sync): YT[n][m] = sum_k W1[n,k] X[m,k] ============
// CTA: 256 batch rows (8 warps x 32). Warp: full n=112 x its 32 m rows.
__global__ __launch_bounds__(256) void gemm1_mma_kernel(const float* __restrict__ X)
{
    const int tid  = threadIdx.x;
    const int warp = tid >> 5;
    const int lane = tid & 31;
    const int q = lane >> 2, r = lane & 3;
    const int m0w = blockIdx.x * 256 + warp * 32;

    float acc[NMT][4][4];
#pragma unroll
    for (int mt = 0; mt < NMT; ++mt)
#pragma unroll
        for (int nt = 0; nt < 4; ++nt)
#pragma unroll
            for (int i = 0; i < 4; ++i) acc[mt][nt][i] = 0.f;

    // X row pointers for the 4 n-tiles (batch rows)
    const float* xr[4];
#pragma unroll
    for (int nt = 0; nt < 4; ++nt)
        xr[nt] = X + (size_t)(m0w + nt * 8 + q) * N_IN + r;

    const float4* __restrict__ Ah = g_ApkHi;
    const float4* __restrict__ Al = g_ApkLo;

    for (int s = 0; s < NKS; ++s) {
        // B fragments from X: split in registers
        uint32_t bh[4][2], bl[4][2];
#pragma unroll
        for (int nt = 0; nt < 4; ++nt) {
            const float x0 = xr[nt][s * 8];
            const float x1 = xr[nt][s * 8 + 4];
            split_tf32(x0, bh[nt][0], bl[nt][0]);
            split_tf32(x1, bh[nt][1], bl[nt][1]);
        }

#pragma unroll
        for (int mt = 0; mt < NMT; ++mt) {
            const float4 ah4 = Ah[(s * NMT + mt) * 32 + lane];
            const float4 al4 = Al[(s * NMT + mt) * 32 + lane];
            const uint32_t ah[4] = {
                __float_as_uint(ah4.x), __float_as_uint(ah4.y),
                __float_as_uint(ah4.z), __float_as_uint(ah4.w) };
            const uint32_t al[4] = {
                __float_as_uint(al4.x), __float_as_uint(al4.y),
                __float_as_uint(al4.z), __float_as_uint(al4.w) };
            // pass 1: hi*hi (4 independent chains)
#pragma unroll
            for (int nt = 0; nt < 4; ++nt)
                mma_tf32(acc[mt][nt][0], acc[mt][nt][1], acc[mt][nt][2], acc[mt][nt][3],
                         ah[0], ah[1], ah[2], ah[3], bh[nt][0], bh[nt][1]);
            // pass 2: hi*lo
#pragma unroll
            for (int nt = 0; nt < 4; ++nt)
                mma_tf32(acc[mt][nt][0], acc[mt][nt][1], acc[mt][nt][2], acc[mt][nt][3],
                         ah[0], ah[1], ah[2], ah[3], bl[nt][0], bl[nt][1]);
            // pass 3: lo*hi
#pragma unroll
            for (int nt = 0; nt < 4; ++nt)
                mma_tf32(acc[mt][nt][0], acc[mt][nt][1], acc[mt][nt][2], acc[mt][nt][3],
                         al[0], al[1], al[2], al[3], bh[nt][0], bh[nt][1]);
        }
    }

    // epilogue -> YT[n][m], float2 stores (cols even)
#pragma unroll
    for (int mt = 0; mt < NMT; ++mt) {
        const int n0 = mt * 16 + q;
#pragma unroll
        for (int nt = 0; nt < 4; ++nt) {
            const int m = m0w + nt * 8 + 2 * r;
            if (n0 < N_HID)
                *reinterpret_cast<float2*>(g_YT + (size_t)n0 * M_TOT + m) =
                    make_float2(acc[mt][nt][0], acc[mt][nt][1]);
            if (n0 + 8 < N_HID)
                *reinterpret_cast<float2*>(g_YT + (size_t)(n0 + 8) * M_TOT + m) =
                    make_float2(acc[mt][nt][2], acc[mt][nt][3]);
        }
    }
}

// ============ Phase A: layer-1 scan, thread = (h, b), walks t ============
__global__ __launch_bounds__(256) void scan1_kernel(
    const float* __restrict__ w_syn1, const float* __restrict__ b1)
{
    const int gid = blockIdx.x * 256 + threadIdx.x;   // 0..102399
    const int h = gid >> 10;        // 0..99
    const int b = gid & 1023;

    const float inv1 = 1.f / (1.f + expf(-w_syn1[0]));
    const float bh = b1[h];

    const float* Yp = g_YT  + (size_t)h * M_TOT + (size_t)b * T_STEPS;
    float*       Sp = g_SPT + (size_t)h * M_TOT + (size_t)b * T_STEPS;

    float hs = 0.f, v = 0.f;
#pragma unroll 1
    for (int i = 0; i < T_STEPS / 4; ++i) {
        const float4 yv = *reinterpret_cast<const float4*>(Yp + i * 4);
        const float ya[4] = {yv.x, yv.y, yv.z, yv.w};
        float sp[4];
#pragma unroll
        for (int j = 0; j < 4; ++j) {
            hs = (hs - hs * inv1) + ya[j];          // SynapseFilter 1
            const float h1 = hs + bh;
            v = v + (h1 - v) * 0.5f;                // LIF decay (tau=2)
            const float s = (v >= 1.0f) ? 1.f : 0.f;
            v = v * (1.f - s);                      // hard reset
            sp[j] = s;
        }
        *reinterpret_cast<float4*>(Sp + i * 4) =
            make_float4(sp[0], sp[1], sp[2], sp[3]);
    }
}

// ============ Phase B: H2T[o][m] = sum_h SPT[h][m] * W2[o,h] ============
__global__ __launch_bounds__(256) void gemm2_kernel(const float* __restrict__ W2)
{
    __shared__ float w2t[N_HID * N_OUT];   // w2t[h*10+o]
    const int tid = threadIdx.x;
    for (int i = tid; i < N_HID * N_OUT; i += 256) {
        const int o = i / N_HID, h = i % N_HID;
        w2t[h * N_OUT + o] = W2[i];
    }
    __syncthreads();

    const int m = blockIdx.x * 256 + tid;
    float acc[N_OUT];
#pragma unroll
    for (int o = 0; o < N_OUT; ++o) acc[o] = 0.f;

#pragma unroll 4
    for (int h = 0; h < N_HID; ++h) {
        const float v = g_SPT[(size_t)h * M_TOT + m];
#pragma unroll
        for (int o = 0; o < N_OUT; ++o)
            acc[o] = fmaf(v, w2t[h * N_OUT + o], acc[o]);
    }
#pragma unroll
    for (int o = 0; o < N_OUT; ++o)
        g_H2T[(size_t)o * M_TOT + m] = acc[o];
}

// ============ Phase C: layer-2 scan, thread = (o, b) ============
__global__ __launch_bounds__(256) void scan2_kernel(
    const float* __restrict__ w_syn2, const float* __restrict__ b2,
    float* __restrict__ out)
{
    const int gt = blockIdx.x * 256 + threadIdx.x;   // 0..10239
    const int o  = gt >> 10;
    const int b  = gt & 1023;

    const float inv2 = 1.f / (1.f + expf(-w_syn2[0]));
    const float bo = b2[o];
    const float* hp = g_H2T + (size_t)o * M_TOT + (size_t)b * T_STEPS;

    float hs = 0.f, v = 0.f;
#pragma unroll 1
    for (int i = 0; i < T_STEPS / 4; ++i) {
        const float4 pv = *reinterpret_cast<const float4*>(hp + i * 4);
        const float pa[4] = {pv.x, pv.y, pv.z, pv.w};
#pragma unroll
        for (int j = 0; j < 4; ++j) {
            hs = (hs - hs * inv2) + pa[j];   // SynapseFilter 2
            const float h2 = hs + bo;
            v = v + (h2 - v) * 0.5f;         // LIF 2 (soft reset @thr 0 -> no-op)
        }
    }
    out[b * N_OUT + o] = v;
}

// ---------------- entry ----------------
extern "C" void kernel_launch(void* const* d_in, const int* in_sizes, int n_in,
                              void* d_out, int out_size) {
    const float* x   = (const float*)d_in[0];  // [1024, 100, 784]
    const float* w1s = (const float*)d_in[1];
    const float* W1  = (const float*)d_in[2];  // [100, 784]
    const float* b1  = (const float*)d_in[3];
    const float* w2s = (const float*)d_in[4];
    const float* W2  = (const float*)d_in[5];  // [10, 100]
    const float* b2  = (const float*)d_in[6];
    float* out = (float*)d_out;                // [1024, 10]

    prep_a_kernel<<<(NKS * NMT * 32 + 255) / 256, 256>>>(W1);
    gemm1_mma_kernel<<<M_TOT / 256, 256>>>(x);
    scan1_kernel<<<M_TOT / 256, 256>>>(w1s, b1);
    gemm2_kernel<<<M_TOT / 256, 256>>>(W2);
    scan2_kernel<<<(B_BATCH * N_OUT) / 256, 256>>>(w2s, b2, out);
}